// round 13
// baseline (speedup 1.0000x reference)
#include <cuda_runtime.h>
#include <cuda_fp16.h>
#include <math.h>

#define N_ROWS 1024
#define M_ROWS 1024
#define DD 256
#define QS 268     // score-kernel shared stride

__device__ float g_q[N_ROWS * DD];
__device__ float g_k[M_ROWS * DD];
__device__ float g_e[N_ROWS * M_ROWS];         // unnormalized exp of scores
__device__ float g_frpT[DD * M_ROWS];          // frp transposed [d-perm][m]
__device__ float g_rowpart[32 * N_ROWS];       // per-mtile rowsum partials
__device__ float g_ctxpart[8 * N_ROWS * DD];   // K-split raw ctx partials
__device__ float g_ctx[N_ROWS * DD];
__device__ float g_sppart[4 * N_ROWS];         // per-dtile sp partials

typedef unsigned long long ull;

__device__ __forceinline__ __half2 tanh_h2(__half2 x) {
    unsigned xi = *(unsigned*)&x, yi;
    asm("tanh.approx.f16x2 %0, %1;" : "=r"(yi) : "r"(xi));
    return *(__half2*)&yi;
}
__device__ __forceinline__ ull fma2(ull a, ull b, ull c) {
    ull d;
    asm("fma.rn.f32x2 %0, %1, %2, %3;" : "=l"(d) : "l"(a), "l"(b), "l"(c));
    return d;
}
__device__ __forceinline__ void unpack2(ull v, float& lo, float& hi) {
    unsigned a, b;
    asm("mov.b64 {%0, %1}, %2;" : "=r"(a), "=r"(b) : "l"(v));
    lo = __uint_as_float(a);
    hi = __uint_as_float(b);
}
__device__ __forceinline__ void cp16(unsigned dst, const void* src) {
    asm volatile("cp.async.cg.shared.global [%0], [%1], 16;" :: "r"(dst), "l"(src));
}
__device__ __forceinline__ void cp_commit() {
    asm volatile("cp.async.commit_group;" ::: "memory");
}
template <int N>
__device__ __forceinline__ void cp_wait() {
    asm volatile("cp.async.wait_group %0;" :: "n"(N) : "memory");
}

// ---------------------------------------------------------------------------
// GEMM (NT) + frp transpose. z=0: q ; z=1: k ; z=2: transpose frp -> g_frpT
// grid (16, 4, 3), block 256.
// ---------------------------------------------------------------------------
__global__ void gemm_qk_kernel(const float* __restrict__ fr,
                               const float* __restrict__ frp,
                               const float* __restrict__ Ww,
                               const float* __restrict__ Wb,
                               const float* __restrict__ Wpw,
                               const float* __restrict__ Wpb) {
    const int z = blockIdx.z;
    const int tid = threadIdx.x;

    if (z == 2) {
        // Transpose frp into g_frpT[d-permuted][m]; row perm within each
        // 128-d tile: row = (d&7)*16 + (d>>3) (bank-spreads ctx F-reads).
        __shared__ float t[32][33];
#pragma unroll
        for (int tt = 0; tt < 4; tt++) {
            int tile = (blockIdx.x * 4 + blockIdx.y) * 4 + tt;
            int bm = (tile >> 3) * 32, bd32 = (tile & 7) * 32;
            {
                int row = tid >> 3;
                int c4 = (tid & 7) * 4;
                float4 v = *(const float4*)&frp[(bm + row) * DD + bd32 + c4];
                t[row][c4 + 0] = v.x; t[row][c4 + 1] = v.y;
                t[row][c4 + 2] = v.z; t[row][c4 + 3] = v.w;
            }
            __syncthreads();
            {
                int dd = tid >> 3;
                int mi4 = (tid & 7) * 4;
                float4 o;
                o.x = t[mi4 + 0][dd];
                o.y = t[mi4 + 1][dd];
                o.z = t[mi4 + 2][dd];
                o.w = t[mi4 + 3][dd];
                int d = bd32 + dd;
                int tl = d >> 7, dt = d & 127;
                int row_g = tl * 128 + ((dt & 7) << 4) + (dt >> 3);
                *(float4*)&g_frpT[row_g * M_ROWS + bm + mi4] = o;
            }
            __syncthreads();
        }
        return;
    }

    const float* __restrict__ A    = z ? frp : fr;
    const float* __restrict__ B    = z ? Wpw : Ww;
    const float* __restrict__ bias = z ? Wpb : Wb;
    float* out = z ? g_k : g_q;

    const int bn = blockIdx.x * 64;
    const int bj = blockIdx.y * 64;
    const int tx = tid & 15, ty = tid >> 4;

    __shared__ float As[64][33];
    __shared__ float Bs[64][33];

    float acc[4][4];
#pragma unroll
    for (int i = 0; i < 4; i++)
#pragma unroll
        for (int j = 0; j < 4; j++) acc[i][j] = 0.f;

    for (int k0 = 0; k0 < DD; k0 += 32) {
#pragma unroll
        for (int it = 0; it < 2; it++) {
            int idx = tid + it * 256;
            int row = idx >> 3;
            int c4  = (idx & 7) * 4;
            float4 va = *(const float4*)&A[(bn + row) * DD + k0 + c4];
            As[row][c4 + 0] = va.x; As[row][c4 + 1] = va.y;
            As[row][c4 + 2] = va.z; As[row][c4 + 3] = va.w;
            float4 vb = *(const float4*)&B[(bj + row) * DD + k0 + c4];
            Bs[row][c4 + 0] = vb.x; Bs[row][c4 + 1] = vb.y;
            Bs[row][c4 + 2] = vb.z; Bs[row][c4 + 3] = vb.w;
        }
        __syncthreads();
#pragma unroll 8
        for (int kk = 0; kk < 32; kk++) {
            float a[4], b[4];
#pragma unroll
            for (int i = 0; i < 4; i++) a[i] = As[ty * 4 + i][kk];
#pragma unroll
            for (int j = 0; j < 4; j++) b[j] = Bs[tx * 4 + j][kk];
#pragma unroll
            for (int i = 0; i < 4; i++)
#pragma unroll
                for (int j = 0; j < 4; j++) acc[i][j] += a[i] * b[j];
        }
        __syncthreads();
    }

    float4 bv = *(const float4*)&bias[bj + tx * 4];
#pragma unroll
    for (int i = 0; i < 4; i++) {
        float4 o;
        o.x = acc[i][0] + bv.x;
        o.y = acc[i][1] + bv.y;
        o.z = acc[i][2] + bv.z;
        o.w = acc[i][3] + bv.w;
        *(float4*)&out[(bn + ty * 4 + i) * DD + bj + tx * 4] = o;
    }
}

// ---------------------------------------------------------------------------
// Scores + exp via f16x2 tanh (2 elems/MUFU op -> halves the MUFU floor):
// x = q+k in f32 (exact), packed to half2 (rn), tanh.approx.f16x2,
// HFMA2 with w*log2e (half2), half2 accumulators flushed to f32 every 16 d.
// e[n,m] = exp2(s*log2e); no-max softmax (|s| <= 16); w_b cancels.
// grid (32 m-tiles, 16 n-tiles), block 256. Per-thread 4n x 2m tile.
// ---------------------------------------------------------------------------
__global__ void score_kernel(const float* __restrict__ ww) {
    extern __shared__ float smem[];
    float* qs = smem;
    float* ks = smem + 64 * QS;
    unsigned* ws2 = (unsigned*)(smem + 96 * QS);   // 128 half2 (w * log2e)

    const int tid = threadIdx.x;
    const int mt = blockIdx.x;
    const int bm = mt * 32;
    const int bn = blockIdx.y * 64;

#pragma unroll
    for (int it = 0; it < 16; it++) {
        int idx = tid + it * 256;
        int row = idx >> 6;
        int c4  = (idx & 63) * 4;
        *(float4*)&qs[row * QS + c4] = *(const float4*)&g_q[(bn + row) * DD + c4];
    }
#pragma unroll
    for (int it = 0; it < 8; it++) {
        int idx = tid + it * 256;
        int row = idx >> 6;
        int c4  = (idx & 63) * 4;
        *(float4*)&ks[row * QS + c4] = *(const float4*)&g_k[(bm + row) * DD + c4];
    }
    if (tid < 128) {
        const float L2E = 1.44269504f;
        __half2 h = __floats2half2_rn(ww[tid * 2] * L2E, ww[tid * 2 + 1] * L2E);
        ws2[tid] = *(unsigned*)&h;
    }
    __syncthreads();

    const int tx = tid & 15, ty = tid >> 4;
    const float* qp = &qs[(ty * 4) * QS];
    const float* kp = &ks[(tx * 2) * QS];

    float facc[4][2];
#pragma unroll
    for (int i = 0; i < 4; i++) { facc[i][0] = 0.f; facc[i][1] = 0.f; }

    for (int dg = 0; dg < 16; dg++) {          // 16 groups of 16 d
        __half2 hacc[4][2];
#pragma unroll
        for (int i = 0; i < 4; i++)
#pragma unroll
            for (int j = 0; j < 2; j++) hacc[i][j] = __floats2half2_rn(0.f, 0.f);

#pragma unroll
        for (int d4i = 0; d4i < 4; d4i++) {    // 4 d per step
            int d4 = dg * 4 + d4i;
            unsigned w01u = ws2[d4 * 2], w23u = ws2[d4 * 2 + 1];
            __half2 w01 = *(__half2*)&w01u, w23 = *(__half2*)&w23u;
            float4 qv[4], kv[2];
#pragma unroll
            for (int i = 0; i < 4; i++) qv[i] = *(const float4*)&qp[i * QS + d4 * 4];
#pragma unroll
            for (int j = 0; j < 2; j++) kv[j] = *(const float4*)&kp[j * QS + d4 * 4];
#pragma unroll
            for (int i = 0; i < 4; i++)
#pragma unroll
                for (int j = 0; j < 2; j++) {
                    __half2 xa = __floats2half2_rn(qv[i].x + kv[j].x,
                                                   qv[i].y + kv[j].y);
                    __half2 xb = __floats2half2_rn(qv[i].z + kv[j].z,
                                                   qv[i].w + kv[j].w);
                    hacc[i][j] = __hfma2(tanh_h2(xa), w01, hacc[i][j]);
                    hacc[i][j] = __hfma2(tanh_h2(xb), w23, hacc[i][j]);
                }
        }
        // Flush half2 partials to f32
#pragma unroll
        for (int i = 0; i < 4; i++)
#pragma unroll
            for (int j = 0; j < 2; j++) {
                float2 f = __half22float2(hacc[i][j]);
                facc[i][j] += f.x + f.y;
            }
    }

    // Epilogue: exp2, store e, per-row partial sums (half-warp owns a row)
#pragma unroll
    for (int i = 0; i < 4; i++) {
        float e0 = exp2f(facc[i][0]);
        float e1 = exp2f(facc[i][1]);
        int n = bn + ty * 4 + i;
        *(float2*)&g_e[n * M_ROWS + bm + tx * 2] = make_float2(e0, e1);
        float rs = e0 + e1;
        rs += __shfl_xor_sync(0xffffffffu, rs, 1);
        rs += __shfl_xor_sync(0xffffffffu, rs, 2);
        rs += __shfl_xor_sync(0xffffffffu, rs, 4);
        rs += __shfl_xor_sync(0xffffffffu, rs, 8);
        if (tx == 0) g_rowpart[mt * N_ROWS + n] = rs;
    }
}

// ---------------------------------------------------------------------------
// K-split context GEMM, m-paired FFMA2 (R12-verified: 20us).
// grid (16 n-tiles, 2 d-tiles, 8 K-slices) = 256 blocks, 256 threads.
// Block tile 64n x 128d x 128m; thread tile 4n x 8d.
// ---------------------------------------------------------------------------
#define EF 132
#define E_STAGE (64 * EF)
#define F_STAGE (128 * EF)
#define CG_SMEM_FLOATS (E_STAGE + F_STAGE)

__global__ __launch_bounds__(256, 2)
void ctx_gemm_kernel() {
    extern __shared__ float sm[];
    float* Es = sm;
    float* Fs = sm + E_STAGE;

    const int tid = threadIdx.x, tx = tid & 15, ty = tid >> 4;
    const int bn = blockIdx.x * 64;
    const int bd = blockIdx.y * 128;
    const int mz = blockIdx.z * 128;
    const unsigned es_u = (unsigned)__cvta_generic_to_shared(Es);
    const unsigned fs_u = (unsigned)__cvta_generic_to_shared(Fs);

#pragma unroll
    for (int j = 0; j < 8; j++) {
        int idx = tid + j * 256;
        int row = idx >> 5;
        int c4 = (idx & 31) * 4;
        cp16(es_u + (unsigned)((row * EF + c4) * 4),
             g_e + (bn + row) * M_ROWS + mz + c4);
    }
#pragma unroll
    for (int j = 0; j < 16; j++) {
        int idx = tid + j * 256;
        int row = idx >> 5;
        int c4 = (idx & 31) * 4;
        cp16(fs_u + (unsigned)((row * EF + c4) * 4),
             g_frpT + (bd + row) * M_ROWS + mz + c4);
    }
    cp_commit();

    ull acc[4][8];
#pragma unroll
    for (int r = 0; r < 4; r++)
#pragma unroll
        for (int j = 0; j < 8; j++) acc[r][j] = 0ull;

    cp_wait<0>();
    __syncthreads();

    const float* Ep = Es + (ty * 4) * EF;
    const float* Fp = Fs + tx * EF;

#pragma unroll 2
    for (int mg = 0; mg < 32; mg++) {
        ulonglong2 ea[4];
#pragma unroll
        for (int r = 0; r < 4; r++)
            ea[r] = *(const ulonglong2*)&Ep[r * EF + mg * 4];
#pragma unroll
        for (int h = 0; h < 2; h++) {
            ulonglong2 fb[4];
#pragma unroll
            for (int j = 0; j < 4; j++)
                fb[j] = *(const ulonglong2*)&Fp[((h * 4 + j) * 16) * EF + mg * 4];
#pragma unroll
            for (int r = 0; r < 4; r++)
#pragma unroll
                for (int j = 0; j < 4; j++) {
                    acc[r][h * 4 + j] = fma2(ea[r].x, fb[j].x, acc[r][h * 4 + j]);
                    acc[r][h * 4 + j] = fma2(ea[r].y, fb[j].y, acc[r][h * 4 + j]);
                }
        }
    }

    float* outp = g_ctxpart + blockIdx.z * (N_ROWS * DD);
#pragma unroll
    for (int r = 0; r < 4; r++) {
        int n = bn + ty * 4 + r;
        float4 v0, v1;
        float lo, hi;
        unpack2(acc[r][0], lo, hi); v0.x = lo + hi;
        unpack2(acc[r][1], lo, hi); v0.y = lo + hi;
        unpack2(acc[r][2], lo, hi); v0.z = lo + hi;
        unpack2(acc[r][3], lo, hi); v0.w = lo + hi;
        unpack2(acc[r][4], lo, hi); v1.x = lo + hi;
        unpack2(acc[r][5], lo, hi); v1.y = lo + hi;
        unpack2(acc[r][6], lo, hi); v1.z = lo + hi;
        unpack2(acc[r][7], lo, hi); v1.w = lo + hi;
        *(float4*)&outp[n * DD + bd + tx * 8] = v0;
        *(float4*)&outp[n * DD + bd + tx * 8 + 4] = v1;
    }
}

// ---------------------------------------------------------------------------
// Fold: sinv (local), ctx = (sum_z ctxpart[z]) * sinv ; sp = ctx . wp_w.
// grid (32 n-tiles, 4 d-tiles), 256 threads.
// ---------------------------------------------------------------------------
__global__ void fold_kernel(const float* __restrict__ wpw) {
    __shared__ float sinv[32];
    const int tid = threadIdx.x, tx = tid & 15, ty = tid >> 4;
    const int bn = blockIdx.x * 32, bd = blockIdx.y * 64;

    if (tid < 32) {
        float s = 0.f;
#pragma unroll
        for (int p = 0; p < 32; p++) s += g_rowpart[p * N_ROWS + bn + tid];
        sinv[tid] = 1.f / s;
    }
    __syncthreads();

    float4 wv4 = *(const float4*)&wpw[bd + tx * 4];
    const int r0 = ty * 2;
#pragma unroll
    for (int r = 0; r < 2; r++) {
        int n = bn + r0 + r;
        int off = n * DD + bd + tx * 4;
        float4 v = make_float4(0.f, 0.f, 0.f, 0.f);
#pragma unroll
        for (int z = 0; z < 8; z++) {
            float4 p = *(const float4*)&g_ctxpart[z * (N_ROWS * DD) + off];
            v.x += p.x; v.y += p.y; v.z += p.z; v.w += p.w;
        }
        float is = sinv[r0 + r];
        v.x *= is; v.y *= is; v.z *= is; v.w *= is;
        *(float4*)&g_ctx[off] = v;
        float pv = v.x * wv4.x + v.y * wv4.y + v.z * wv4.z + v.w * wv4.w;
        pv += __shfl_xor_sync(0xffffffffu, pv, 1);
        pv += __shfl_xor_sync(0xffffffffu, pv, 2);
        pv += __shfl_xor_sync(0xffffffffu, pv, 4);
        pv += __shfl_xor_sync(0xffffffffu, pv, 8);
        if (tx == 0) g_sppart[blockIdx.y * N_ROWS + n] = pv;
    }
}

// ---------------------------------------------------------------------------
// Final: sp = sum of d-tile partials; softmax over n (wp_b cancels); pool.
// 1 block, 1024 threads.
// ---------------------------------------------------------------------------
__global__ void final_kernel(float* __restrict__ out) {
    __shared__ float sp[1024];
    __shared__ float red[32];
    __shared__ float part[16 * 256];

    const int tid = threadIdx.x, lane = tid & 31, wid = tid >> 5;

    float v = g_sppart[tid] + g_sppart[N_ROWS + tid]
            + g_sppart[2 * N_ROWS + tid] + g_sppart[3 * N_ROWS + tid];
    float mx = v;
#pragma unroll
    for (int o = 16; o; o >>= 1) mx = fmaxf(mx, __shfl_xor_sync(0xffffffffu, mx, o));
    if (lane == 0) red[wid] = mx;
    __syncthreads();
    if (tid < 32) {
        float m2 = red[lane];
#pragma unroll
        for (int o = 16; o; o >>= 1) m2 = fmaxf(m2, __shfl_xor_sync(0xffffffffu, m2, o));
        if (lane == 0) red[0] = m2;
    }
    __syncthreads();
    float gmx = red[0];
    __syncthreads();

    float e = __expf(v - gmx);
    float s = e;
#pragma unroll
    for (int o = 16; o; o >>= 1) s += __shfl_xor_sync(0xffffffffu, s, o);
    if (lane == 0) red[wid] = s;
    __syncthreads();
    if (tid < 32) {
        float s2 = red[lane];
#pragma unroll
        for (int o = 16; o; o >>= 1) s2 += __shfl_xor_sync(0xffffffffu, s2, o);
        if (lane == 0) red[0] = s2;
    }
    __syncthreads();
    sp[tid] = e / red[0];
    __syncthreads();

    const int p = tid >> 6, dg = tid & 63;
    const int d0 = dg * 4;
    float4 acc = make_float4(0.f, 0.f, 0.f, 0.f);
#pragma unroll 4
    for (int t = 0; t < 64; t++) {
        int n = p * 64 + t;
        float a = sp[n];
        float4 f = *(const float4*)&g_ctx[n * DD + d0];
        acc.x += a * f.x; acc.y += a * f.y;
        acc.z += a * f.z; acc.w += a * f.w;
    }
    *(float4*)&part[p * 256 + d0] = acc;
    __syncthreads();

    if (tid < 256) {
        float r = 0.f;
#pragma unroll
        for (int bb = 0; bb < 16; bb++) r += part[bb * 256 + tid];
        out[tid] = r;
    }
}

// ---------------------------------------------------------------------------
extern "C" void kernel_launch(void* const* d_in, const int* in_sizes, int n_in,
                              void* d_out, int out_size) {
    const float* fr  = (const float*)d_in[0];
    const float* frp = (const float*)d_in[1];
    const float* Ww  = (const float*)d_in[2];
    const float* Wb  = (const float*)d_in[3];
    const float* Wpw = (const float*)d_in[4];
    const float* Wpb = (const float*)d_in[5];
    const float* ww  = (const float*)d_in[6];
    // d_in[7] = w_b, d_in[9] = wp_b: scalar biases cancel inside softmax — unused.
    const float* wpw = (const float*)d_in[8];
    float* out = (float*)d_out;

    const int score_smem = (96 * QS + 256) * (int)sizeof(float);   // ~103.9KB
    const int cg_smem    = CG_SMEM_FLOATS * (int)sizeof(float);    // ~101.4KB
    cudaFuncSetAttribute(score_kernel,
                         cudaFuncAttributeMaxDynamicSharedMemorySize, score_smem);
    cudaFuncSetAttribute(ctx_gemm_kernel,
                         cudaFuncAttributeMaxDynamicSharedMemorySize, cg_smem);

    gemm_qk_kernel<<<dim3(16, 4, 3), 256>>>(fr, frp, Ww, Wb, Wpw, Wpb);  // idx 0
    score_kernel<<<dim3(32, 16), 256, score_smem>>>(ww);                 // idx 1
    ctx_gemm_kernel<<<dim3(16, 2, 8), 256, cg_smem>>>();                 // idx 2
    fold_kernel<<<dim3(32, 4), 256>>>(wpw);                              // idx 3 (profiled)
    final_kernel<<<1, 1024>>>(out);                                      // idx 4
}